// round 3
// baseline (speedup 1.0000x reference)
#include <cuda_runtime.h>
#include <math.h>

#define HH 512
#define WW 512
#define NB 64
#define PD 15
#define TH 128
#define TW 128
#define SH (TH + 2 * PD)   // 158
#define SW (TW + 2 * PD)   // 158
#define SMP 160            // mask tile row stride (floats)
#define VSP 161            // vsum tile row stride (floats)
#define NTHREADS 512
#define TILES_X (WW / TW)  // 4
#define TILES_Y (HH / TH)  // 4
#define NPART (TILES_X * TILES_Y)  // 16 tiles per image

// Per-CTA partials, fully overwritten every launch (no zeroing needed).
__device__ float g_part[NB * NPART * 2];

__global__ __launch_bounds__(NTHREADS, 1)
void fused_kernel(const float* __restrict__ pred, const float* __restrict__ mask) {
    extern __shared__ float shm[];
    float* sm = shm;                 // [SH][SMP] mask halo tile
    float* vs = shm + SH * SMP;      // [TH][VSP] vertical box sums -> avg (in place)

    const int t  = threadIdx.x;
    const int c0 = blockIdx.x * TW;
    const int r0 = blockIdx.y * TH;
    const int b  = blockIdx.z;
    const float* mbase = mask + (size_t)b * HH * WW;

    // ---- Phase 1: load 158x158 mask halo tile (zero-padded outside image) ----
    for (int idx = t; idx < SH * SW; idx += NTHREADS) {
        int r = idx / SW;
        int c = idx - r * SW;
        int gr = r0 - PD + r;
        int gc = c0 - PD + c;
        float v = 0.f;
        if ((unsigned)gr < HH && (unsigned)gc < WW)
            v = __ldg(mbase + gr * WW + gc);
        sm[r * SMP + c] = v;
    }
    __syncthreads();

    // ---- Phase 2: vertical 31-tap running sums, all 158 columns, 2 row-halves ----
    if (t < 2 * SW) {
        int h  = (t >= SW);
        int c  = t - h * SW;
        int rs = h * (TH / 2);
        float s = 0.f;
        #pragma unroll
        for (int j = 0; j < 30; ++j) s += sm[(rs + j) * SMP + c];
        #pragma unroll 4
        for (int r = rs; r < rs + TH / 2; ++r) {
            s += sm[(r + 30) * SMP + c];
            vs[r * VSP + c] = s;              // window rows [r .. r+30] of sm
            s -= sm[r * SMP + c];
        }
    }
    __syncthreads();

    // ---- Phase 3: horizontal 31-tap running sums -> avg, in place (1 thread/row) ----
    if (t < TH) {
        const float inv = 1.0f / 961.0f;
        float* vrow = vs + t * VSP;
        float s = 0.f;
        #pragma unroll
        for (int j = 0; j < 30; ++j) s += vrow[j];
        #pragma unroll 8
        for (int c = 0; c < TW; ++c) {
            s += vrow[c + 30];
            float avg = s * inv;
            s -= vrow[c];
            vrow[c] = avg;                    // vrow[c] consumed; safe same-thread
        }
    }
    __syncthreads();

    // ---- Phase 4: fused elementwise + block reduction ----
    const float* pbase = pred + ((size_t)b * HH + r0) * WW + c0;
    float fi = 0.f, fu = 0.f;
    #pragma unroll
    for (int i4 = t; i4 < TH * TW / 4; i4 += NTHREADS) {
        int r = i4 >> 5;             // 32 float4 per row
        int c = (i4 & 31) * 4;
        float4 p4 = *reinterpret_cast<const float4*>(pbase + r * WW + c);
        float pr[4] = {p4.x, p4.y, p4.z, p4.w};
        #pragma unroll
        for (int q = 0; q < 4; ++q) {
            int cc = c + q;
            float mk   = sm[(r + PD) * SMP + cc + PD];
            float avg  = vs[r * VSP + cc];
            float weit = fmaf(5.f, fabsf(avg - mk), 1.f);
            float p    = __frcp_rn(1.f + __expf(-pr[q]));
            fi = fmaf(p * mk, weit, fi);
            fu = fmaf(p + mk, weit, fu);
        }
    }

    // block reduce 512 -> 1
    __shared__ float s_i[16], s_u[16];
    #pragma unroll
    for (int o = 16; o; o >>= 1) {
        fi += __shfl_down_sync(0xffffffffu, fi, o);
        fu += __shfl_down_sync(0xffffffffu, fu, o);
    }
    int wid = t >> 5, lane = t & 31;
    if (lane == 0) { s_i[wid] = fi; s_u[wid] = fu; }
    __syncthreads();
    if (wid == 0) {
        float ti = (lane < 16) ? s_i[lane] : 0.f;
        float tu = (lane < 16) ? s_u[lane] : 0.f;
        #pragma unroll
        for (int o = 8; o; o >>= 1) {
            ti += __shfl_down_sync(0xffffffffu, ti, o);
            tu += __shfl_down_sync(0xffffffffu, tu, o);
        }
        if (lane == 0) {
            int part = blockIdx.y * TILES_X + blockIdx.x;
            g_part[(b * NPART + part) * 2 + 0] = ti;
            g_part[(b * NPART + part) * 2 + 1] = tu;
        }
    }
}

__global__ void finalize_kernel(float* __restrict__ out) {
    int t = threadIdx.x;   // 64 threads
    double w = 0.0;
    if (t < NB) {
        double it = 0.0, un = 0.0;
        #pragma unroll
        for (int p = 0; p < NPART; ++p) {
            it += (double)g_part[(t * NPART + p) * 2 + 0];
            un += (double)g_part[(t * NPART + p) * 2 + 1];
        }
        w = 1.0 - (2.0 * it + 0.5) / (un + 0.5);
    }
    #pragma unroll
    for (int o = 16; o; o >>= 1) w += __shfl_down_sync(0xffffffffu, w, o);
    __shared__ double sh[2];
    if ((t & 31) == 0) sh[t >> 5] = w;
    __syncthreads();
    if (t == 0) out[0] = (float)((sh[0] + sh[1]) / (double)NB);
}

extern "C" void kernel_launch(void* const* d_in, const int* in_sizes, int n_in,
                              void* d_out, int out_size) {
    const float* pred = (const float*)d_in[0];
    const float* mask = (const float*)d_in[1];
    float* out = (float*)d_out;

    const int smem_bytes = (SH * SMP + TH * VSP) * (int)sizeof(float);  // 183,552
    cudaFuncSetAttribute(fused_kernel,
                         cudaFuncAttributeMaxDynamicSharedMemorySize, smem_bytes);

    fused_kernel<<<dim3(TILES_X, TILES_Y, NB), NTHREADS, smem_bytes>>>(pred, mask);
    finalize_kernel<<<1, 64>>>(out);
}

// round 4
// speedup vs baseline: 1.5780x; 1.5780x over previous
#include <cuda_runtime.h>
#include <math.h>

#define HH 512
#define WW 512
#define NB 64
#define PD 15
#define RB 64                 // rows per band
#define BANDS (HH / RB)       // 8
#define GG 4                  // rows per smem group
#define NGROUPS (RB / GG)     // 16
#define NTH 512
#define SBW 560               // swizzled buffer width (>= scol(541)+1 = 557)

__device__ __forceinline__ int scol(int c) { return c + (c >> 5); }

// per-(image, band) partials, fully overwritten each launch
__device__ float g_part[NB * BANDS * 2];

__global__ __launch_bounds__(NTH, 3)
void fused_kernel(const float* __restrict__ pred, const float* __restrict__ mask) {
    __shared__ float buf[GG][SBW];
    __shared__ float s_i[16], s_u[16];

    const int t    = threadIdx.x;           // = column
    const int band = blockIdx.x;
    const int b    = blockIdx.y;
    const int r0   = band * RB;
    const float* mb = mask + (size_t)b * HH * WW;
    const float* pb = pred + (size_t)b * HH * WW;

    // zero whole buffer once (halos stay zero; interior overwritten each group)
    for (int i = t; i < GG * SBW; i += NTH) ((float*)buf)[i] = 0.f;

    // vertical running-sum init: rows [r0-15, r0+14]
    float s = 0.f;
    #pragma unroll
    for (int j = 0; j < 2 * PD; ++j) {
        int gr = r0 - PD + j;
        if ((unsigned)gr < HH) s += mb[gr * WW + t];
    }
    __syncthreads();

    const float inv = 1.0f / 961.0f;
    float fi = 0.f, fu = 0.f;

    // phase-B thread mapping (fixed across groups)
    const int rg = t >> 7;                  // 0..3 row-in-group
    const int c0 = (t & 127) * 4;           // 4-column chunk

    for (int g = 0; g < NGROUPS; ++g) {
        const int rbase = r0 + g * GG;

        // prefetch phase-B gmem early (independent of smem)
        const int grB = rbase + rg;
        float4 m4 = *reinterpret_cast<const float4*>(mb + grB * WW + c0);
        float4 p4 = *reinterpret_cast<const float4*>(pb + grB * WW + c0);

        // ---- phase A: vertical sliding window, stage GG colsum rows ----
        #pragma unroll
        for (int rr = 0; rr < GG; ++rr) {
            int gr = rbase + rr;
            float lead = (gr + PD < HH) ? mb[(gr + PD) * WW + t] : 0.f;
            s += lead;
            buf[rr][scol(t + PD)] = s;      // window rows [gr-15, gr+15]
            float trail = (gr - PD >= 0) ? mb[(gr - PD) * WW + t] : 0.f;
            s -= trail;
        }
        __syncthreads();

        // ---- phase B: horizontal window + fused elementwise ----
        float hs = 0.f;
        #pragma unroll
        for (int j = 0; j < 31; ++j) hs += buf[rg][scol(c0 + j)];

        float mk[4] = {m4.x, m4.y, m4.z, m4.w};
        float pr[4] = {p4.x, p4.y, p4.z, p4.w};
        #pragma unroll
        for (int q = 0; q < 4; ++q) {
            float avg  = hs * inv;
            float weit = fmaf(5.f, fabsf(avg - mk[q]), 1.f);
            float p    = __frcp_rn(1.f + __expf(-pr[q]));
            fi = fmaf(p * mk[q], weit, fi);
            fu = fmaf(p + mk[q], weit, fu);
            hs += buf[rg][scol(c0 + q + 31)] - buf[rg][scol(c0 + q)];
        }
        __syncthreads();                    // before next group overwrites buf
    }

    // ---- block reduce 512 -> 1 ----
    #pragma unroll
    for (int o = 16; o; o >>= 1) {
        fi += __shfl_down_sync(0xffffffffu, fi, o);
        fu += __shfl_down_sync(0xffffffffu, fu, o);
    }
    int wid = t >> 5, lane = t & 31;
    if (lane == 0) { s_i[wid] = fi; s_u[wid] = fu; }
    __syncthreads();
    if (wid == 0) {
        float ti = (lane < 16) ? s_i[lane] : 0.f;
        float tu = (lane < 16) ? s_u[lane] : 0.f;
        #pragma unroll
        for (int o = 8; o; o >>= 1) {
            ti += __shfl_down_sync(0xffffffffu, ti, o);
            tu += __shfl_down_sync(0xffffffffu, tu, o);
        }
        if (lane == 0) {
            g_part[(b * BANDS + band) * 2 + 0] = ti;
            g_part[(b * BANDS + band) * 2 + 1] = tu;
        }
    }
}

__global__ void finalize_kernel(float* __restrict__ out) {
    int t = threadIdx.x;   // 64 threads
    double w = 0.0;
    if (t < NB) {
        double it = 0.0, un = 0.0;
        #pragma unroll
        for (int p = 0; p < BANDS; ++p) {
            it += (double)g_part[(t * BANDS + p) * 2 + 0];
            un += (double)g_part[(t * BANDS + p) * 2 + 1];
        }
        w = 1.0 - (2.0 * it + 0.5) / (un + 0.5);
    }
    #pragma unroll
    for (int o = 16; o; o >>= 1) w += __shfl_down_sync(0xffffffffu, w, o);
    __shared__ double sh[2];
    if ((t & 31) == 0) sh[t >> 5] = w;
    __syncthreads();
    if (t == 0) out[0] = (float)((sh[0] + sh[1]) / (double)NB);
}

extern "C" void kernel_launch(void* const* d_in, const int* in_sizes, int n_in,
                              void* d_out, int out_size) {
    const float* pred = (const float*)d_in[0];
    const float* mask = (const float*)d_in[1];
    float* out = (float*)d_out;

    fused_kernel<<<dim3(BANDS, NB), NTH>>>(pred, mask);
    finalize_kernel<<<1, 64>>>(out);
}

// round 6
// speedup vs baseline: 1.9259x; 1.2204x over previous
#include <cuda_runtime.h>
#include <math.h>

#define HH 512
#define WW 512
#define NB 64
#define PD 15
#define RB 64                 // rows per band (per CTA)
#define BANDS (HH / RB)       // 8
#define GG 8                  // rows per smem group
#define NGROUPS (RB / GG)     // 8
#define NTH 512
#define SBW 560               // swizzled row width (>= scol(542)+1 = 559)
#define NBLOCKS (BANDS * NB)  // 512

__device__ __forceinline__ int scol(int c) { return c + (c >> 5); }

__device__ float g_part[NB * BANDS * 2];
__device__ unsigned int g_count = 0;

__global__ __launch_bounds__(NTH, 3)
void fused_kernel(const float* __restrict__ pred, const float* __restrict__ mask,
                  float* __restrict__ out) {
    __shared__ float buf[2][GG][SBW];
    __shared__ float s_i[16], s_u[16];
    __shared__ bool amLast;

    const int t    = threadIdx.x;           // = column for phase A
    const int band = blockIdx.x;
    const int b    = blockIdx.y;
    const int r0   = band * RB;
    const float* mb = mask + (size_t)b * HH * WW;
    const float* pb = pred + (size_t)b * HH * WW;

    // zero both buffers once (halo regions stay zero thereafter)
    #pragma unroll
    for (int i = t; i < 2 * GG * SBW; i += NTH) ((float*)buf)[i] = 0.f;

    // vertical running-sum init: rows [r0-15, r0+14] of column t
    float s = 0.f;
    #pragma unroll
    for (int j = 0; j < 2 * PD; ++j) {
        int gr = r0 - PD + j;
        if ((unsigned)gr < HH) s += mb[gr * WW + t];
    }

    // BARRIER: zeroing must complete before any staged interior write
    // (round-5 bug: prologue writes raced with the zero loop)
    __syncthreads();

    // ---- prologue: phase A for group 0 into buf[0] ----
    {
        const int rbase = r0;
        #pragma unroll
        for (int rr = 0; rr < GG; ++rr) {
            int gr = rbase + rr;
            float lead = (gr + PD < HH) ? mb[(gr + PD) * WW + t] : 0.f;
            s += lead;
            buf[0][rr][scol(t + PD)] = s;
            float trail = (gr - PD >= 0) ? mb[(gr - PD) * WW + t] : 0.f;
            s -= trail;
        }
    }
    __syncthreads();

    const float inv = 1.0f / 961.0f;
    float fi = 0.f, fu = 0.f;

    // phase-B mapping: 64 threads per row, 8 cols per thread
    const int rg = t >> 6;                  // 0..7 row-in-group
    const int c0 = (t & 63) * 8;            // 8-column chunk

    for (int g = 0; g < NGROUPS; ++g) {
        // ---- phase A for group g+1 into buf[(g+1)&1] (overlaps phase B below) ----
        if (g + 1 < NGROUPS) {
            const int rbase = r0 + (g + 1) * GG;
            float* bw = &buf[(g + 1) & 1][0][0];
            #pragma unroll
            for (int rr = 0; rr < GG; ++rr) {
                int gr = rbase + rr;
                float lead = (gr + PD < HH) ? mb[(gr + PD) * WW + t] : 0.f;
                s += lead;
                bw[rr * SBW + scol(t + PD)] = s;
                float trail = (gr - PD >= 0) ? mb[(gr - PD) * WW + t] : 0.f;
                s -= trail;
            }
        }

        // ---- phase B for group g from buf[g&1] ----
        {
            const int grB = r0 + g * GG + rg;
            const float* br = &buf[g & 1][rg][0];
            float4 m4a = *reinterpret_cast<const float4*>(mb + grB * WW + c0);
            float4 m4b = *reinterpret_cast<const float4*>(mb + grB * WW + c0 + 4);
            float4 p4a = *reinterpret_cast<const float4*>(pb + grB * WW + c0);
            float4 p4b = *reinterpret_cast<const float4*>(pb + grB * WW + c0 + 4);

            float hs = 0.f;
            #pragma unroll
            for (int j = 0; j < 31; ++j) hs += br[scol(c0 + j)];

            float mk[8] = {m4a.x, m4a.y, m4a.z, m4a.w, m4b.x, m4b.y, m4b.z, m4b.w};
            float pr[8] = {p4a.x, p4a.y, p4a.z, p4a.w, p4b.x, p4b.y, p4b.z, p4b.w};
            #pragma unroll
            for (int q = 0; q < 8; ++q) {
                float avg  = hs * inv;
                float weit = fmaf(5.f, fabsf(avg - mk[q]), 1.f);
                float p    = __frcp_rn(1.f + __expf(-pr[q]));
                fi = fmaf(p * mk[q], weit, fi);
                fu = fmaf(p + mk[q], weit, fu);
                hs += br[scol(c0 + q + 31)] - br[scol(c0 + q)];
            }
        }
        __syncthreads();
    }

    // ---- block reduce 512 -> 1 ----
    #pragma unroll
    for (int o = 16; o; o >>= 1) {
        fi += __shfl_down_sync(0xffffffffu, fi, o);
        fu += __shfl_down_sync(0xffffffffu, fu, o);
    }
    int wid = t >> 5, lane = t & 31;
    if (lane == 0) { s_i[wid] = fi; s_u[wid] = fu; }
    __syncthreads();
    if (wid == 0) {
        float ti = (lane < 16) ? s_i[lane] : 0.f;
        float tu = (lane < 16) ? s_u[lane] : 0.f;
        #pragma unroll
        for (int o = 8; o; o >>= 1) {
            ti += __shfl_down_sync(0xffffffffu, ti, o);
            tu += __shfl_down_sync(0xffffffffu, tu, o);
        }
        if (lane == 0) {
            g_part[(b * BANDS + band) * 2 + 0] = ti;
            g_part[(b * BANDS + band) * 2 + 1] = tu;
            __threadfence();
            unsigned int done = atomicAdd(&g_count, 1u);
            amLast = (done == NBLOCKS - 1);
        }
    }
    __syncthreads();

    // ---- last CTA: finalize ----
    if (amLast) {
        double w = 0.0;
        if (t < NB) {
            double it = 0.0, un = 0.0;
            #pragma unroll
            for (int p = 0; p < BANDS; ++p) {
                it += (double)g_part[(t * BANDS + p) * 2 + 0];
                un += (double)g_part[(t * BANDS + p) * 2 + 1];
            }
            w = 1.0 - (2.0 * it + 0.5) / (un + 0.5);
        }
        #pragma unroll
        for (int o = 16; o; o >>= 1) w += __shfl_down_sync(0xffffffffu, w, o);
        __shared__ double sh[2];
        if (t < 64 && (t & 31) == 0) sh[t >> 5] = w;
        __syncthreads();
        if (t == 0) {
            out[0] = (float)((sh[0] + sh[1]) / (double)NB);
            g_count = 0;   // reset for next graph replay
        }
    }
}

extern "C" void kernel_launch(void* const* d_in, const int* in_sizes, int n_in,
                              void* d_out, int out_size) {
    const float* pred = (const float*)d_in[0];
    const float* mask = (const float*)d_in[1];
    float* out = (float*)d_out;

    fused_kernel<<<dim3(BANDS, NB), NTH>>>(pred, mask, out);
}